// round 7
// baseline (speedup 1.0000x reference)
#include <cuda_runtime.h>
#include <math_constants.h>

// out[n] = h( max_l min_f max_c |A[n,l,c] - B[c,f]| ),  h(D) = t/(1+t)^2, t = exp(-10 D)
// Identity: sigmoid(10x)*sigmoid(-10x) = h(|x|); h strictly decreasing => all
// reductions commute through h. Single fused kernel, counter-based finalize;
// all __device__ state returns to zero each launch (graph-replay safe).

#define NB 64
#define LB 512
#define FB 2048
#define THREADS 256
#define LCHUNKS 8
#define L_PER 64                 // l's per block (lane covers 2: li and li+32)
#define F_PER 256                // f's per warp (8 warps cover FB)

__device__ unsigned int g_dmax[NB];    // float bits of per-n running max; 0 at rest
__device__ unsigned int g_count[NB];   // arrival counters; 0 at rest

__device__ __forceinline__ unsigned long long pack2(float x, float y) {
    unsigned long long r;
    asm("mov.b64 %0, {%1, %2};" : "=l"(r) : "f"(x), "f"(y));
    return r;
}

// Packed fp32x2 add (Blackwell): one fma-pipe instruction for both channels.
__device__ __forceinline__ float2 addf32x2(unsigned long long a, unsigned long long b) {
    unsigned long long d;
    asm("add.rn.f32x2 %0, %1, %2;" : "=l"(d) : "l"(a), "l"(b));
    float lo, hi;
    asm("mov.b64 {%0, %1}, %2;" : "=f"(lo), "=f"(hi) : "l"(d));
    return make_float2(lo, hi);
}

__device__ __forceinline__ float cheb(float2 d) {
    return fmaxf(fabsf(d.x), fabsf(d.y));   // FMNMX with |.| modifiers
}

__global__ __launch_bounds__(THREADS, 4)   // cap 64 regs: allow deep LDS batching
void psl_fused_kernel(const float* __restrict__ A, const float* __restrict__ B,
                      float* __restrict__ out) {
    __shared__ __align__(16) float2 sB[FB];   // NEGATED, interleaved; 16 KB
    __shared__ float sRedA[THREADS];
    __shared__ float sRedB[THREADS];

    const int n      = blockIdx.x;   // 0..63
    const int lchunk = blockIdx.y;   // 0..7
    const int tid    = threadIdx.x;

    // Stage negated B so the packed add computes (a - b).
    #pragma unroll
    for (int i = tid; i < FB; i += THREADS) {
        sB[i] = make_float2(-B[i], -B[FB + i]);
    }
    __syncthreads();

    const int fq = tid >> 5;         // f-octant 0..7 (warp-uniform -> smem broadcast)
    const int li = tid & 31;
    const int l0 = lchunk * L_PER + li;
    const int l1 = l0 + 32;

    const float2 a0 = reinterpret_cast<const float2*>(A)[(size_t)n * LB + l0];
    const float2 a1 = reinterpret_cast<const float2*>(A)[(size_t)n * LB + l1];
    const unsigned long long ap0 = pack2(a0.x, a0.y);
    const unsigned long long ap1 = pack2(a1.x, a1.y);

    // 16-byte smem reads: each ulonglong2 holds two f's worth of (b0,b1) pairs.
    const ulonglong2* p = reinterpret_cast<const ulonglong2*>(sB + fq * F_PER);

    // 2 independent min chains per l.
    float m00 = CUDART_INF_F, m01 = CUDART_INF_F;
    float m10 = CUDART_INF_F, m11 = CUDART_INF_F;

    #pragma unroll 2
    for (int j = 0; j < F_PER / 2; j += 4) {   // 8 f per body: 4 LDS.128
        ulonglong2 q0 = p[j + 0];
        ulonglong2 q1 = p[j + 1];
        ulonglong2 q2 = p[j + 2];
        ulonglong2 q3 = p[j + 3];

        m00 = fminf(m00, cheb(addf32x2(ap0, q0.x)));
        m01 = fminf(m01, cheb(addf32x2(ap0, q0.y)));
        m10 = fminf(m10, cheb(addf32x2(ap1, q0.x)));
        m11 = fminf(m11, cheb(addf32x2(ap1, q0.y)));

        m00 = fminf(m00, cheb(addf32x2(ap0, q1.x)));
        m01 = fminf(m01, cheb(addf32x2(ap0, q1.y)));
        m10 = fminf(m10, cheb(addf32x2(ap1, q1.x)));
        m11 = fminf(m11, cheb(addf32x2(ap1, q1.y)));

        m00 = fminf(m00, cheb(addf32x2(ap0, q2.x)));
        m01 = fminf(m01, cheb(addf32x2(ap0, q2.y)));
        m10 = fminf(m10, cheb(addf32x2(ap1, q2.x)));
        m11 = fminf(m11, cheb(addf32x2(ap1, q2.y)));

        m00 = fminf(m00, cheb(addf32x2(ap0, q3.x)));
        m01 = fminf(m01, cheb(addf32x2(ap0, q3.y)));
        m10 = fminf(m10, cheb(addf32x2(ap1, q3.x)));
        m11 = fminf(m11, cheb(addf32x2(ap1, q3.y)));
    }

    sRedA[tid] = fminf(m00, m01);   // partial min over f-octant, l0
    sRedB[tid] = fminf(m10, m11);   // partial min over f-octant, l1
    __syncthreads();

    if (tid < 32) {
        // Min across the 8 f-octants for l = li and l = li+32, then max over l.
        float vA = sRedA[tid];
        float vB = sRedB[tid];
        #pragma unroll
        for (int k = 32; k < THREADS; k += 32) {
            vA = fminf(vA, sRedA[tid + k]);
            vB = fminf(vB, sRedB[tid + k]);
        }
        float v = fmaxf(vA, vB);
        #pragma unroll
        for (int off = 16; off; off >>= 1)
            v = fmaxf(v, __shfl_xor_sync(0xffffffffu, v, off));

        if (tid == 0) {
            // Nonnegative floats: uint bit-pattern compare == float compare.
            atomicMax(&g_dmax[n], __float_as_uint(v));
            __threadfence();   // publish max before signaling arrival
            unsigned int old = atomicAdd(&g_count[n], 1u);
            if (old == LCHUNKS - 1) {
                __threadfence();
                // Read-and-reset: state returns to 0 for the next graph replay.
                unsigned int dbits = atomicExch(&g_dmax[n], 0u);
                atomicExch(&g_count[n], 0u);
                float D = __uint_as_float(dbits);
                // h(D) = t/(1+t)^2, t = exp(-10D) <= 1.
                float t = expf(-10.0f * D);
                float u = 1.0f + t;
                out[n] = t / (u * u);
            }
        }
    }
}

extern "C" void kernel_launch(void* const* d_in, const int* in_sizes, int n_in,
                              void* d_out, int out_size) {
    const float* A = (const float*)d_in[0];
    const float* B = (const float*)d_in[1];
    // Defensive: identify by element count (A = 64*512*2 = 65536, B = 2*2048 = 4096).
    if (n_in >= 2 && in_sizes[0] == 4096 && in_sizes[1] == 65536) {
        const float* tmp = A; A = B; B = tmp;
    }
    float* out = (float*)d_out;

    dim3 grid(NB, LCHUNKS);   // 64 x 8 = 512 blocks, 4/SM co-resident, one wave
    psl_fused_kernel<<<grid, THREADS>>>(A, B, out);
}